// round 16
// baseline (speedup 1.0000x reference)
#include <cuda_runtime.h>
#include <cuda_bf16.h>
#include <math.h>

#define NN 50000
#define ROWSP 50048
#define DD 256
#define EE 800000
#define NCLS 47
#define NLAYER 3
#define NB2 782
#define CSRB 148

#define SWZ(x) ((x) ^ (((x) >> 3) & 0x70))

// ---- fused kernel smem layout (per CTA, 2 CTAs/SM) ----
#define FS_B 32768
#define RSUM_OFF 98304
#define FSMEM 98816

// ---------------- device scratch ----------------
__device__ uint4 g_whi4[100 * 2048];
__device__ unsigned g_ximg_hi[4 * ROWSP * 32];
__device__ unsigned g_zimg_hi[4 * ROWSP * 32];
__device__ unsigned g_himg_hi[4 * ROWSP * 32];
__device__ unsigned g_himg_lo[4 * ROWSP * 32];
__device__ float g_wc[256 * NCLS];
__device__ float g_bc[NCLS];
__device__ int g_cnti[NN];          // static zero-init; self-zeroed each run
__device__ int g_off[NN + 1];
__device__ int g_cur[NN];
__device__ int g_csr[EE];
__device__ int g_partial[CSRB];
__device__ int g_pscan[CSRB];
__device__ unsigned g_bar;

struct SlotTab { const uint4* p[36]; };

static __device__ __forceinline__ unsigned smem_u32(const void* p) {
    unsigned a;
    asm("{ .reg .u64 t; cvta.to.shared.u64 t, %1; cvt.u32.u64 %0, t; }" : "=r"(a) : "l"(p));
    return a;
}
static __device__ __forceinline__ void ldsm4(unsigned r[4], unsigned addr) {
    asm volatile("ldmatrix.sync.aligned.m8n8.x4.shared.b16 {%0,%1,%2,%3}, [%4];"
                 : "=r"(r[0]), "=r"(r[1]), "=r"(r[2]), "=r"(r[3]) : "r"(addr));
}
static __device__ __forceinline__ void mma16816(float d[4], const unsigned a[4],
                                                unsigned b0, unsigned b1) {
    asm volatile(
        "mma.sync.aligned.m16n8k16.row.col.f32.bf16.bf16.f32 "
        "{%0,%1,%2,%3}, {%4,%5,%6,%7}, {%8,%9}, {%0,%1,%2,%3};"
        : "+f"(d[0]), "+f"(d[1]), "+f"(d[2]), "+f"(d[3])
        : "r"(a[0]), "r"(a[1]), "r"(a[2]), "r"(a[3]), "r"(b0), "r"(b1));
}
#define CPA(dst, src) \
    asm volatile("cp.async.cg.shared.global [%0], [%1], 16;" :: "r"(dst), "l"(src) : "memory")
#define CP_COMMIT() asm volatile("cp.async.commit_group;" ::: "memory")
template <int N>
static __device__ __forceinline__ void cp_wait() {
    asm volatile("cp.async.wait_group %0;" :: "n"(N) : "memory");
}

static __device__ __forceinline__ void bsplit(float v, unsigned& h, unsigned& l) {
    __nv_bfloat16 hb = __float2bfloat16(v);
    h = __bfloat16_as_ushort(hb);
    l = __bfloat16_as_ushort(__float2bfloat16(v - __bfloat162float(hb)));
}
static __device__ __forceinline__ unsigned bhi(float v) {
    return (unsigned)__bfloat16_as_ushort(__float2bfloat16(v));
}
static __device__ __forceinline__ float bf2f(unsigned short u) {
    return __bfloat162float(__ushort_as_bfloat16(u));
}
static __device__ __forceinline__ unsigned img_idx(int chunk, int row, int lc) {
    return ((unsigned)chunk * ROWSP + (unsigned)row) * 32u +
           ((((unsigned)(lc * 2)) ^ (((unsigned)row & 7u) << 4)) >> 2);
}
static __device__ __forceinline__ void img_write2(unsigned* __restrict__ hi,
                                                  unsigned* __restrict__ lo, int chunk,
                                                  int row, int lc, float v0, float v1) {
    unsigned h0, l0, h1, l1;
    bsplit(v0, h0, l0);
    bsplit(v1, h1, l1);
    unsigned idx = img_idx(chunk, row, lc);
    hi[idx] = h0 | (h1 << 16);
    lo[idx] = l0 | (l1 << 16);
}
static __device__ __forceinline__ void img_write_hi(unsigned* __restrict__ hi, int chunk,
                                                    int row, int lc, float v0, float v1) {
    hi[img_idx(chunk, row, lc)] = bhi(v0) | (bhi(v1) << 16);
}
static __device__ __forceinline__ float2 img_read2(const unsigned* __restrict__ hi,
                                                   const unsigned* __restrict__ lo, int chunk,
                                                   int row, int lc) {
    unsigned idx = img_idx(chunk, row, lc);
    unsigned h = hi[idx], l = lo[idx];
    return make_float2(bf2f((unsigned short)(h & 0xffff)) + bf2f((unsigned short)(l & 0xffff)),
                       bf2f((unsigned short)(h >> 16)) + bf2f((unsigned short)(l >> 16)));
}

// ---------------- setup: weight prep + x image + combined post (ONE launch) ----------------
__global__ void setup_kernel(const float* __restrict__ linl, const float* __restrict__ linr,
                             const float* __restrict__ w1, const float* __restrict__ wa,
                             const float* __restrict__ wb, const float* __restrict__ w2,
                             const float* __restrict__ post, const float* __restrict__ postb1,
                             const float* __restrict__ postW2, const float* __restrict__ postb2,
                             const float* __restrict__ X,
                             unsigned short* __restrict__ dhi, unsigned* __restrict__ xih,
                             float* __restrict__ wc, float* __restrict__ bc) {
    int b = blockIdx.x;
    if (b < 6400) {
        int idx = b * 256 + threadIdx.x;
        int m = idx >> 16;
        int rem = idx & 65535;
        int n = rem & 255, k = rem >> 8;
        const float* W;
        int chunk;
        if (m < 3)       { W = linl + (size_t)m * 65536;       chunk = 0  + m * 8 + (k >> 6); }
        else if (m < 6)  { W = linr + (size_t)(m - 3) * 65536; chunk = 4  + (m - 3) * 8 + (k >> 6); }
        else if (m < 9)  { W = w1 + (size_t)(m - 6) * 65536;   chunk = 24 + (m - 6) * 4 + (k >> 6); }
        else if (m < 15) { W = wa + (size_t)(m - 9) * 65536;   chunk = 36 + (m - 9) * 4 + (k >> 6); }
        else if (m < 21) { W = wb + (size_t)(m - 15) * 65536;  chunk = 60 + (m - 15) * 4 + (k >> 6); }
        else             { W = w2 + (size_t)(m - 21) * 65536;  chunk = 84 + (m - 21) * 4 + (k >> 6); }
        float v = W[(size_t)k * 256 + n];
        unsigned off = (unsigned)chunk * 32768u + SWZ((unsigned)(n * 128 + (k & 63) * 2));
        dhi[off >> 1] = (unsigned short)bhi(v);
    } else if (b < 31400) {
        int idx = (b - 6400) * 256 + threadIdx.x;   // < NN*128 exactly
        int row = idx >> 7, p = idx & 127;
        float v0 = X[(size_t)row * 256 + p * 2];
        float v1 = X[(size_t)row * 256 + p * 2 + 1];
        img_write_hi(xih, (p * 2) >> 6, row, (p * 2) & 63, v0, v1);
    } else {
        // combined post weights: Wc[k][c2] = sum_c postW1[k][c] * postW2[c][c2]
        int c2 = b - 31400;            // 0..46
        int k = threadIdx.x;           // 0..255
        float s = 0.f;
        for (int c = 0; c < 256; c++)
            s = fmaf(post[(size_t)k * 256 + c], postW2[(size_t)c * NCLS + c2], s);
        wc[k * NCLS + c2] = s;
        if (k == 0) {
            float t = postb2[c2];
            for (int c = 0; c < 256; c++)
                t = fmaf(postb1[c], postW2[(size_t)c * NCLS + c2], t);
            bc[c2] = t;
        }
    }
}

// ---------------- single-kernel CSR build (persistent grid + sw barrier) ----------------
static __device__ __forceinline__ void gridbar() {
    __syncthreads();
    __threadfence();
    if (threadIdx.x == 0) {
        unsigned arr = atomicAdd(&g_bar, 1u);
        unsigned target = (arr / CSRB + 1u) * CSRB;
        while (*(volatile unsigned*)&g_bar < target) { }
    }
    __syncthreads();
}

__global__ void csr_kernel(const int* __restrict__ src, const int* __restrict__ dst,
                           int* __restrict__ cnt, int* __restrict__ off,
                           int* __restrict__ cur, int* __restrict__ csr) {
    __shared__ int sdata[256];
    const int b = blockIdx.x, t = threadIdx.x;
    for (int e = b * 256 + t; e < EE; e += CSRB * 256)
        atomicAdd(&cnt[dst[e]], 1);
    gridbar();
    int n0 = (b * 256 + t) * 2;
    int c0 = (n0 < NN) ? cnt[n0] : 0;
    int c1 = (n0 + 1 < NN) ? cnt[n0 + 1] : 0;
    if (n0 < NN) cnt[n0] = 0;
    if (n0 + 1 < NN) cnt[n0 + 1] = 0;
    int ts = c0 + c1;
    sdata[t] = ts;
    __syncthreads();
#pragma unroll
    for (int o = 1; o < 256; o <<= 1) {
        int v = (t >= o) ? sdata[t - o] : 0;
        __syncthreads();
        sdata[t] += v;
        __syncthreads();
    }
    int bexcl = sdata[t] - ts;
    if (t == 255) g_partial[b] = sdata[t];
    gridbar();
    if (b == 0) {
        int v = (t < CSRB) ? g_partial[t] : 0;
        sdata[t] = v;
        __syncthreads();
#pragma unroll
        for (int o = 1; o < 256; o <<= 1) {
            int w = (t >= o) ? sdata[t - o] : 0;
            __syncthreads();
            sdata[t] += w;
            __syncthreads();
        }
        if (t < CSRB) g_pscan[t] = sdata[t] - v;
        if (t == 0) off[0] = 0;
    }
    gridbar();
    int base = g_pscan[b] + bexcl;
    if (n0 < NN) {
        cur[n0] = base;
        off[n0 + 1] = base + c0;
        if (n0 + 1 < NN) {
            cur[n0 + 1] = base + c0;
            if (n0 + 2 <= NN) off[n0 + 2] = base + c0 + c1;
        }
    }
    gridbar();
    for (int e = b * 256 + t; e < EE; e += CSRB * 256) {
        int p = atomicAdd(&cur[dst[e]], 1);
        csr[p] = src[e];
    }
}

// ---------------- gather (hi-only, 8-wide MLP) ----------------
__global__ void gather_img(const unsigned* __restrict__ xih,
                           const int* __restrict__ off, const int* __restrict__ csr,
                           unsigned* __restrict__ zih) {
    int w = (blockIdx.x * 256 + threadIdx.x) >> 5;
    int d = w >> 2, c = w & 3;
    if (d >= NN) return;
    int lane = threadIdx.x & 31;
    int b = off[d], e = off[d + 1];
    const unsigned* __restrict__ base = xih + (size_t)c * ROWSP * 32u;
    float s0 = 0.f, s1 = 0.f;
    int j = b;
    for (; j + 8 <= e; j += 8) {
        int r[8];
#pragma unroll
        for (int q = 0; q < 8; q++) r[q] = __ldg(&csr[j + q]);
        unsigned v[8];
#pragma unroll
        for (int q = 0; q < 8; q++)
            v[q] = __ldg(&base[(unsigned)r[q] * 32u + ((unsigned)lane ^ (((unsigned)r[q] & 7u) << 2))]);
#pragma unroll
        for (int q = 0; q < 8; q++) {
            s0 += bf2f((unsigned short)(v[q] & 0xffff));
            s1 += bf2f((unsigned short)(v[q] >> 16));
        }
    }
    for (; j + 2 <= e; j += 2) {
        int r0 = __ldg(&csr[j]), r1 = __ldg(&csr[j + 1]);
        unsigned v0 = __ldg(&base[(unsigned)r0 * 32u + ((unsigned)lane ^ (((unsigned)r0 & 7u) << 2))]);
        unsigned v1 = __ldg(&base[(unsigned)r1 * 32u + ((unsigned)lane ^ (((unsigned)r1 & 7u) << 2))]);
        s0 += bf2f((unsigned short)(v0 & 0xffff)) + bf2f((unsigned short)(v1 & 0xffff));
        s1 += bf2f((unsigned short)(v0 >> 16)) + bf2f((unsigned short)(v1 >> 16));
    }
    if (j < e) {
        int r0 = __ldg(&csr[j]);
        unsigned v0 = __ldg(&base[(unsigned)r0 * 32u + ((unsigned)lane ^ (((unsigned)r0 & 7u) << 2))]);
        s0 += bf2f((unsigned short)(v0 & 0xffff));
        s1 += bf2f((unsigned short)(v0 >> 16));
    }
    float iv = 1.f / fmaxf((float)(e - b), 1.f);
    img_write_hi(zih, c, d, lane * 2, s0 * iv, s1 * iv);
}

// ---- M64 MMA micro-kernel: one 8KB A chunk (64 rows, k64) vs one 32KB B chunk ----
// warp tile 16(M) x 128(N): wm0 = (wid&3)*16, wn0 = (wid>>2)*128. acc[16][4].
static __device__ __forceinline__ void mma_chunk(unsigned abase, unsigned bbase,
                                                 float (&acc)[16][4], int wm0, int wn0,
                                                 int lane) {
    const int lrow = lane & 15;
    const int lk = (lane >> 4) * 8;
#pragma unroll
    for (int ks = 0; ks < 4; ks++) {
        const int k0 = ks * 16;
        unsigned ahi[4];
        {
            unsigned off = SWZ((unsigned)((wm0 + lrow) * 128 + (k0 + lk) * 2));
            ldsm4(ahi, abase + off);
        }
#pragma unroll
        for (int hp = 0; hp < 4; hp++) {
            unsigned bb[2][4];
#pragma unroll
            for (int q = 0; q < 2; q++) {
                int g = hp * 2 + q;
                unsigned off = SWZ((unsigned)((wn0 + g * 16 + lrow) * 128 + (k0 + lk) * 2));
                ldsm4(bb[q], bbase + off);
            }
#pragma unroll
            for (int q = 0; q < 2; q++)
#pragma unroll
                for (int r0 = 0; r0 < 2; r0++)
                    mma16816(acc[(hp * 2 + q) * 2 + r0], ahi, bb[q][r0], bb[q][r0 + 2]);
        }
    }
}

// ---------------- fused layer kernel (M64, 256 threads, 2 CTAs/SM) ----------------
// 32 K-64 slots (+4 post): stage st = s>>2, A chunk = s&3.
// Stage order: cat-x, cat-z, w1, wa0, wb0, wa1, wb1, w2 [, post]
__global__ void __launch_bounds__(256, 2)
fused_layer(unsigned* __restrict__ ximg_hi, const unsigned* __restrict__ zimg_hi,
            SlotTab tab, int nslots,
            const float* __restrict__ bl, const float* __restrict__ br,
            const float* __restrict__ b1,
            const float* __restrict__ ba0, const float* __restrict__ g0,
            const float* __restrict__ be0, const float* __restrict__ bb0,
            const float* __restrict__ ba1, const float* __restrict__ g1,
            const float* __restrict__ be1, const float* __restrict__ bb1,
            const float* __restrict__ b2, const float* __restrict__ postb, float bnscale,
            unsigned* __restrict__ himg_hi, unsigned* __restrict__ himg_lo,
            float* __restrict__ pp) {
    extern __shared__ char smem[];
    const unsigned sb = smem_u32(smem);
    const int tid = threadIdx.x, wid = tid >> 5, lane = tid & 31;
    const int bm0 = blockIdx.x * 64;
    const int wm0 = (wid & 3) * 16;
    const int wn0 = (wid >> 2) * 128;
    const int tr = lane >> 2;
    const int tc2 = (lane & 3) * 2;
    const bool haspost = (nslots > 32);

    float acc[16][4];
    auto zero_acc = [&]() {
#pragma unroll
        for (int a = 0; a < 16; a++)
#pragma unroll
            for (int c = 0; c < 4; c++) acc[a][c] = 0.f;
    };
    zero_acc();

    auto issue_B = [&](int s) {   // 32KB, no commit
        if (s >= nslots) return;
        const char* src = (const char*)tab.p[s];
        unsigned dstb = sb + FS_B + (unsigned)(s & 1) * 32768u;
#pragma unroll
        for (int i = 0; i < 8; i++) {
            int u = tid + i * 256;
            CPA(dstb + u * 16, src + u * 16);
        }
    };
    auto issue_z = [&](int c) {   // 8KB hi-only into A chunk c
        const char* gh = (const char*)(zimg_hi + ((size_t)c * ROWSP + bm0) * 32);
        unsigned cb = sb + (unsigned)c * 8192u;
#pragma unroll
        for (int i = 0; i < 2; i++) {
            int u = tid + i * 256;
            CPA(cb + u * 16, gh + u * 16);
        }
    };
    auto slot = [&](int s, int ah, int zc) {
        cp_wait<0>();
        __syncthreads();
        issue_B(s + 1);
        if (zc >= 0) issue_z(zc);
        CP_COMMIT();
        mma_chunk(sb + (unsigned)ah * 8192u, sb + FS_B + (unsigned)(s & 1) * 32768u,
                  acc, wm0, wn0, lane);
    };
    auto run4 = [&](int s0) {
#pragma unroll 1
        for (int c = 0; c < 4; c++) slot(s0 + c, c, -1);
    };
    auto conv_img = [&]() {   // acc -> smem A image (hi only); caller syncs BEFORE
#pragma unroll
        for (int ni = 0; ni < 16; ni++) {
            int cg = wn0 + ni * 8 + tc2;
            unsigned cb = (unsigned)(cg >> 6) * 8192u;
            int lc = cg & 63;
            float* d = acc[ni];
            unsigned off = SWZ((unsigned)((wm0 + tr) * 128 + lc * 2));
            *(unsigned*)(smem + cb + off) = bhi(d[0]) | (bhi(d[1]) << 16);
            off = SWZ((unsigned)((wm0 + 8 + tr) * 128 + lc * 2));
            *(unsigned*)(smem + cb + off) = bhi(d[2]) | (bhi(d[3]) << 16);
        }
    };

    // ---- prologue: x image (hi only, 4x8KB) + B slot 0 ----
#pragma unroll
    for (int c = 0; c < 4; c++) {
        const char* gh = (const char*)(ximg_hi + ((size_t)c * ROWSP + bm0) * 32);
        unsigned cb = sb + (unsigned)c * 8192u;
#pragma unroll
        for (int i = 0; i < 2; i++) {
            int u = tid + i * 256;
            CPA(cb + u * 16, gh + u * 16);
        }
    }
    CP_COMMIT();
    issue_B(0);
    CP_COMMIT();

    // ---- cat: slots 0-3 (x), 4-7 (z); z chunk s-1 prefetched at slots 1..4 ----
#pragma unroll 1
    for (int s = 0; s < 8; s++)
        slot(s, s & 3, (s >= 1 && s <= 4) ? (s - 1) : -1);
    __syncthreads();
#pragma unroll
    for (int ni = 0; ni < 16; ni++) {
        int cg = wn0 + ni * 8 + tc2;
        float* d = acc[ni];
        float a0 = bl[cg] + br[cg], a1 = bl[cg + 1] + br[cg + 1];
        d[0] += a0; d[1] += a1; d[2] += a0; d[3] += a1;
    }
    conv_img(); zero_acc();

    // ---- w1: slots 8-11 -> h0 (write himg) ----
    run4(8);
    __syncthreads();
#pragma unroll
    for (int ni = 0; ni < 16; ni++) {
        int cg = wn0 + ni * 8 + tc2;
        float* d = acc[ni];
        d[0] += b1[cg]; d[1] += b1[cg + 1]; d[2] += b1[cg]; d[3] += b1[cg + 1];
        int ra = bm0 + wm0 + tr;
        img_write2(himg_hi, himg_lo, cg >> 6, ra, cg & 63, d[0], d[1]);
        img_write2(himg_hi, himg_lo, cg >> 6, ra + 8, cg & 63, d[2], d[3]);
    }
    conv_img(); zero_acc();

    // ---- blocks: wa j: 12+8j, wb j: 16+8j ----
#pragma unroll 1
    for (int j = 0; j < 2; j++) {
        const float* ba = j ? ba1 : ba0;
        const float* gg = j ? g1 : g0;
        const float* be = j ? be1 : be0;
        const float* bb = j ? bb1 : bb0;
        run4(12 + j * 8);
        __syncthreads();
#pragma unroll
        for (int ni = 0; ni < 16; ni++) {
            int cg = wn0 + ni * 8 + tc2;
            float* d = acc[ni];
            float ga = gg[cg], gb = gg[cg + 1], ea = be[cg], eb = be[cg + 1];
            float a0 = ba[cg], a1 = ba[cg + 1];
            d[0] = fmaf(ga, fmaxf(d[0] + a0, 0.f) * bnscale, ea);
            d[1] = fmaf(gb, fmaxf(d[1] + a1, 0.f) * bnscale, eb);
            d[2] = fmaf(ga, fmaxf(d[2] + a0, 0.f) * bnscale, ea);
            d[3] = fmaf(gb, fmaxf(d[3] + a1, 0.f) * bnscale, eb);
        }
        conv_img(); zero_acc();
        run4(16 + j * 8);
        __syncthreads();
#pragma unroll
        for (int ni = 0; ni < 16; ni++) {
            int cg = wn0 + ni * 8 + tc2;
            float* d = acc[ni];
            int ra = bm0 + wm0 + tr;
            float2 ha = img_read2(himg_hi, himg_lo, cg >> 6, ra, cg & 63);
            float2 hb = img_read2(himg_hi, himg_lo, cg >> 6, ra + 8, cg & 63);
            d[0] += bb[cg] + ha.x; d[1] += bb[cg + 1] + ha.y;
            d[2] += bb[cg] + hb.x; d[3] += bb[cg + 1] + hb.y;
            if (j == 0) {
                img_write2(himg_hi, himg_lo, cg >> 6, ra, cg & 63, d[0], d[1]);
                img_write2(himg_hi, himg_lo, cg >> 6, ra + 8, cg & 63, d[2], d[3]);
            }
        }
        conv_img(); zero_acc();
    }

    // ---- w2: slots 28-31, normalize + relu ----
    run4(28);
    __syncthreads();
#pragma unroll
    for (int ni = 0; ni < 16; ni++) {
        int cg = wn0 + ni * 8 + tc2;
        float* d = acc[ni];
        d[0] += b2[cg]; d[1] += b2[cg + 1]; d[2] += b2[cg]; d[3] += b2[cg + 1];
    }
    {
        float* rsum = (float*)(smem + RSUM_OFF);   // [64 rows][2 halves]
        float ps0 = 0.f, ps1 = 0.f;
#pragma unroll
        for (int ni = 0; ni < 16; ni++) {
            float* d = acc[ni];
            ps0 = fmaf(d[0], d[0], fmaf(d[1], d[1], ps0));
            ps1 = fmaf(d[2], d[2], fmaf(d[3], d[3], ps1));
        }
#pragma unroll
        for (int o = 1; o <= 2; o <<= 1) {
            ps0 += __shfl_xor_sync(0xffffffffu, ps0, o);
            ps1 += __shfl_xor_sync(0xffffffffu, ps1, o);
        }
        int half = wn0 >> 7;
        if ((lane & 3) == 0) {
            rsum[(wm0 + tr) * 2 + half] = ps0;
            rsum[(wm0 + 8 + tr) * 2 + half] = ps1;
        }
        __syncthreads();
        int r0 = wm0 + tr, r1 = r0 + 8;
        float s0 = rsum[r0 * 2] + rsum[r0 * 2 + 1];
        float s1 = rsum[r1 * 2] + rsum[r1 * 2 + 1];
        float c0 = 1.f / fmaxf(sqrtf(s0), 1e-12f);
        float c1 = 1.f / fmaxf(sqrtf(s1), 1e-12f);
#pragma unroll
        for (int ni = 0; ni < 16; ni++) {
            float* d = acc[ni];
            d[0] = fmaxf(d[0] * c0, 0.f); d[1] = fmaxf(d[1] * c0, 0.f);
            d[2] = fmaxf(d[2] * c1, 0.f); d[3] = fmaxf(d[3] * c1, 0.f);
        }
    }
    if (!haspost) {
#pragma unroll
        for (int ni = 0; ni < 16; ni++) {
            int cg = wn0 + ni * 8 + tc2;
            int ra = bm0 + wm0 + tr;
            float* d = acc[ni];
            img_write_hi(ximg_hi, cg >> 6, ra, cg & 63, d[0], d[1]);
            img_write_hi(ximg_hi, cg >> 6, ra + 8, cg & 63, d[2], d[3]);
        }
        return;
    }
    // ---- post stage (unused in this config; kept for codegen parity) ----
    conv_img(); zero_acc();
    __syncthreads();
    run4(32);
    __syncthreads();
#pragma unroll
    for (int ni = 0; ni < 16; ni++) {
        int cg = wn0 + ni * 8 + tc2;
        int ra = bm0 + wm0 + tr;
        int rb = ra + 8;
        float* d = acc[ni];
        float v0 = d[0] + postb[cg], v1 = d[1] + postb[cg + 1];
        float v2 = d[2] + postb[cg], v3 = d[3] + postb[cg + 1];
        if (ra < NN) *(float2*)(pp + (size_t)ra * 256 + cg) = make_float2(v0, v1);
        if (rb < NN) *(float2*)(pp + (size_t)rb * 256 + cg) = make_float2(v2, v3);
    }
}

// ---------------- head: logits = x @ Wc + bc, log_softmax (reads x image) ----------------
__global__ void head_kernel(const unsigned* __restrict__ xih, const float* __restrict__ Wc,
                            const float* __restrict__ bc, float* __restrict__ out) {
    __shared__ float sW[256 * NCLS];
    __shared__ float sb[NCLS];
    int tid = threadIdx.x;
    for (int i = tid; i < 256 * NCLS; i += 256) sW[i] = Wc[i];
    if (tid < NCLS) sb[tid] = bc[tid];
    __syncthreads();

    int wid = tid >> 5, lane = tid & 31;
    int r = blockIdx.x * 8 + wid;
    if (r >= NN) return;

    // lane holds cols {c*64 + lane*2, +1} for chunks c=0..3
    float hreg[8];
#pragma unroll
    for (int c = 0; c < 4; c++) {
        unsigned v = __ldg(&xih[((size_t)c * ROWSP + r) * 32u +
                                ((unsigned)lane ^ (((unsigned)r & 7u) << 2))]);
        hreg[c * 2 + 0] = bf2f((unsigned short)(v & 0xffff));
        hreg[c * 2 + 1] = bf2f((unsigned short)(v >> 16));
    }

    int c0 = lane;
    int c1 = lane + 32;
    int c1m = (c1 < NCLS) ? c1 : (NCLS - 1);
    float acc0 = sb[c0];
    float acc1 = sb[c1m];
#pragma unroll
    for (int e = 0; e < 8; e++) {
        int ch = e >> 1, hf = e & 1;
        for (int l = 0; l < 32; l++) {
            float hv = __shfl_sync(0xffffffffu, hreg[e], l);
            int k = ch * 64 + l * 2 + hf;
            acc0 = fmaf(hv, sW[k * NCLS + c0], acc0);
            acc1 = fmaf(hv, sW[k * NCLS + c1m], acc1);
        }
    }
    float m = fmaxf(acc0, (c1 < NCLS) ? acc1 : -3.4e38f);
#pragma unroll
    for (int o = 16; o > 0; o >>= 1) m = fmaxf(m, __shfl_xor_sync(0xffffffffu, m, o));
    float es = expf(acc0 - m) + ((c1 < NCLS) ? expf(acc1 - m) : 0.f);
#pragma unroll
    for (int o = 16; o > 0; o >>= 1) es += __shfl_xor_sync(0xffffffffu, es, o);
    float lse = m + logf(es);
    out[(size_t)r * NCLS + c0] = acc0 - lse;
    if (c1 < NCLS) out[(size_t)r * NCLS + c1] = acc1 - lse;
}

// ---------------- host orchestration ----------------
extern "C" void kernel_launch(void* const* d_in, const int* in_sizes, int n_in,
                              void* d_out, int out_size) {
    const float* x_in      = (const float*)d_in[0];
    const int* ei          = (const int*)d_in[1];
    const float* lin_l_W   = (const float*)d_in[2];
    const float* lin_l_b   = (const float*)d_in[3];
    const float* lin_r_W   = (const float*)d_in[4];
    const float* lin_r_b   = (const float*)d_in[5];
    const float* mlp_W1    = (const float*)d_in[6];
    const float* mlp_b1    = (const float*)d_in[7];
    const float* blk_Wa    = (const float*)d_in[8];
    const float* blk_ba    = (const float*)d_in[9];
    const float* blk_gamma = (const float*)d_in[10];
    const float* blk_beta  = (const float*)d_in[11];
    const float* blk_Wb    = (const float*)d_in[12];
    const float* blk_bb    = (const float*)d_in[13];
    const float* mlp_W2    = (const float*)d_in[14];
    const float* mlp_b2    = (const float*)d_in[15];
    const float* post_W1   = (const float*)d_in[16];
    const float* post_b1   = (const float*)d_in[17];
    const float* post_W2   = (const float*)d_in[18];
    const float* post_b2   = (const float*)d_in[19];
    float* out = (float*)d_out;

    uint4* whi;
    unsigned *xih, *zih, *hih, *hil;
    float *wc, *bc;
    int *cnti, *offp, *curp, *csrp;
    cudaGetSymbolAddress((void**)&whi, g_whi4);
    cudaGetSymbolAddress((void**)&xih, g_ximg_hi);
    cudaGetSymbolAddress((void**)&zih, g_zimg_hi);
    cudaGetSymbolAddress((void**)&hih, g_himg_hi);
    cudaGetSymbolAddress((void**)&hil, g_himg_lo);
    cudaGetSymbolAddress((void**)&wc, g_wc);
    cudaGetSymbolAddress((void**)&bc, g_bc);
    cudaGetSymbolAddress((void**)&cnti, g_cnti);
    cudaGetSymbolAddress((void**)&offp, g_off);
    cudaGetSymbolAddress((void**)&curp, g_cur);
    cudaGetSymbolAddress((void**)&csrp, g_csr);

    cudaFuncSetAttribute(fused_layer, cudaFuncAttributeMaxDynamicSharedMemorySize, FSMEM);

    const float bnscale = rsqrtf(1.0f + 1e-5f);
    const int* src = ei;
    const int* dst = ei + EE;

    // 1: setup (weights [24 matrices] + x image + combined post head)
    setup_kernel<<<31400 + NCLS, 256>>>(
        lin_l_W, lin_r_W, mlp_W1, blk_Wa, blk_Wb, mlp_W2,
        post_W1, post_b1, post_W2, post_b2, x_in,
        (unsigned short*)whi, xih, wc, bc);
    // 2: CSR (count+scan+fill, one persistent kernel)
    csr_kernel<<<CSRB, 256>>>(src, dst, cnti, offp, curp, csrp);

    for (int i = 0; i < NLAYER; i++) {
        // 3: gather (hi only, 8-wide)
        gather_img<<<(NN + 1) / 2, 256>>>(xih, offp, csrp, zih);

        SlotTab tab;
        int s = 0;
        auto push = [&](int base) {   // one 256x256 matrix = 4 slots of 32KB
            for (int c = 0; c < 4; c++) tab.p[s++] = whi + (size_t)(base + c) * 2048;
        };
        push(i * 8);                 // cat-x (lin_l)           slots 0-3
        push(i * 8 + 4);             // cat-z (lin_r)           slots 4-7
        push(24 + i * 4);            // w1                      slots 8-11
        push(36 + (2 * i) * 4);      // wa0                     slots 12-15
        push(60 + (2 * i) * 4);      // wb0                     slots 16-19
        push(36 + (2 * i + 1) * 4);  // wa1                     slots 20-23
        push(60 + (2 * i + 1) * 4);  // wb1                     slots 24-27
        push(84 + i * 4);            // w2                      slots 28-31

        size_t bo0 = ((size_t)i * 2) * 256, bo1 = ((size_t)i * 2 + 1) * 256;
        // 4: fused layer (nslots=32 for ALL layers -> !haspost path; post folded into head)
        fused_layer<<<NB2, 256, FSMEM>>>(
            xih, zih, tab, 32,
            lin_l_b + (size_t)i * 256, lin_r_b + (size_t)i * 256,
            mlp_b1 + (size_t)i * 256,
            blk_ba + bo0, blk_gamma + bo0, blk_beta + bo0, blk_bb + bo0,
            blk_ba + bo1, blk_gamma + bo1, blk_beta + bo1, blk_bb + bo1,
            mlp_b2 + (size_t)i * 256, post_b1, bnscale,
            hih, hil, nullptr);
    }

    head_kernel<<<(NN + 7) / 8, 256>>>(xih, wc, bc, out);
}

// round 17
// speedup vs baseline: 1.0894x; 1.0894x over previous
#include <cuda_runtime.h>
#include <cuda_bf16.h>
#include <math.h>

#define NN 50000
#define ROWSP 50048
#define DD 256
#define EE 800000
#define NCLS 47
#define NLAYER 3
#define NB2 782
#define CSRB 148

#define SWZ(x) ((x) ^ (((x) >> 3) & 0x70))

// ---- fused kernel smem layout (per CTA, 2 CTAs/SM) ----
#define FS_B 32768
#define RSUM_OFF 98304
#define FSMEM 98816

// ---------------- device scratch ----------------
__device__ uint4 g_whi4[100 * 2048];
__device__ unsigned g_ximg_hi[4 * ROWSP * 32];
__device__ unsigned g_zimg_hi[4 * ROWSP * 32];
__device__ unsigned g_himg_hi[4 * ROWSP * 32];
__device__ unsigned g_himg_lo[4 * ROWSP * 32];
__device__ float g_wc[256 * NCLS];
__device__ float g_bc[NCLS];
__device__ int g_cnti[NN];          // static zero-init; self-zeroed each run
__device__ int g_off[NN + 1];
__device__ int g_cur[NN];
__device__ int g_csr[EE];
__device__ int g_partial[CSRB];
__device__ int g_pscan[CSRB];
__device__ unsigned g_bar;

struct SlotTab { const uint4* p[36]; };

static __device__ __forceinline__ unsigned smem_u32(const void* p) {
    unsigned a;
    asm("{ .reg .u64 t; cvta.to.shared.u64 t, %1; cvt.u32.u64 %0, t; }" : "=r"(a) : "l"(p));
    return a;
}
static __device__ __forceinline__ void ldsm4(unsigned r[4], unsigned addr) {
    asm volatile("ldmatrix.sync.aligned.m8n8.x4.shared.b16 {%0,%1,%2,%3}, [%4];"
                 : "=r"(r[0]), "=r"(r[1]), "=r"(r[2]), "=r"(r[3]) : "r"(addr));
}
static __device__ __forceinline__ void mma16816(float d[4], const unsigned a[4],
                                                unsigned b0, unsigned b1) {
    asm volatile(
        "mma.sync.aligned.m16n8k16.row.col.f32.bf16.bf16.f32 "
        "{%0,%1,%2,%3}, {%4,%5,%6,%7}, {%8,%9}, {%0,%1,%2,%3};"
        : "+f"(d[0]), "+f"(d[1]), "+f"(d[2]), "+f"(d[3])
        : "r"(a[0]), "r"(a[1]), "r"(a[2]), "r"(a[3]), "r"(b0), "r"(b1));
}
#define CPA(dst, src) \
    asm volatile("cp.async.cg.shared.global [%0], [%1], 16;" :: "r"(dst), "l"(src) : "memory")
#define CP_COMMIT() asm volatile("cp.async.commit_group;" ::: "memory")
template <int N>
static __device__ __forceinline__ void cp_wait() {
    asm volatile("cp.async.wait_group %0;" :: "n"(N) : "memory");
}

static __device__ __forceinline__ void bsplit(float v, unsigned& h, unsigned& l) {
    __nv_bfloat16 hb = __float2bfloat16(v);
    h = __bfloat16_as_ushort(hb);
    l = __bfloat16_as_ushort(__float2bfloat16(v - __bfloat162float(hb)));
}
static __device__ __forceinline__ unsigned bhi(float v) {
    return (unsigned)__bfloat16_as_ushort(__float2bfloat16(v));
}
static __device__ __forceinline__ float bf2f(unsigned short u) {
    return __bfloat162float(__ushort_as_bfloat16(u));
}
static __device__ __forceinline__ unsigned img_idx(int chunk, int row, int lc) {
    return ((unsigned)chunk * ROWSP + (unsigned)row) * 32u +
           ((((unsigned)(lc * 2)) ^ (((unsigned)row & 7u) << 4)) >> 2);
}
static __device__ __forceinline__ void img_write2(unsigned* __restrict__ hi,
                                                  unsigned* __restrict__ lo, int chunk,
                                                  int row, int lc, float v0, float v1) {
    unsigned h0, l0, h1, l1;
    bsplit(v0, h0, l0);
    bsplit(v1, h1, l1);
    unsigned idx = img_idx(chunk, row, lc);
    hi[idx] = h0 | (h1 << 16);
    lo[idx] = l0 | (l1 << 16);
}
static __device__ __forceinline__ void img_write_hi(unsigned* __restrict__ hi, int chunk,
                                                    int row, int lc, float v0, float v1) {
    hi[img_idx(chunk, row, lc)] = bhi(v0) | (bhi(v1) << 16);
}
static __device__ __forceinline__ float2 img_read2(const unsigned* __restrict__ hi,
                                                   const unsigned* __restrict__ lo, int chunk,
                                                   int row, int lc) {
    unsigned idx = img_idx(chunk, row, lc);
    unsigned h = hi[idx], l = lo[idx];
    return make_float2(bf2f((unsigned short)(h & 0xffff)) + bf2f((unsigned short)(l & 0xffff)),
                       bf2f((unsigned short)(h >> 16)) + bf2f((unsigned short)(l >> 16)));
}

// ---------------- setup: Wc/bc (overlapped, coalesced) + weight prep + x image ----------------
// Block map: [0,256) Wc row k=b; 256 bc; [257, 6657) weight prep; [6657, 31657) x image.
__global__ void setup_kernel(const float* __restrict__ linl, const float* __restrict__ linr,
                             const float* __restrict__ w1, const float* __restrict__ wa,
                             const float* __restrict__ wb, const float* __restrict__ w2,
                             const float* __restrict__ post, const float* __restrict__ postb1,
                             const float* __restrict__ postW2, const float* __restrict__ postb2,
                             const float* __restrict__ X,
                             unsigned short* __restrict__ dhi, unsigned* __restrict__ xih,
                             float* __restrict__ wc, float* __restrict__ bc) {
    int b = blockIdx.x;
    if (b < 256) {
        // Wc[b][c2] = sum_c post[b*256+c] * postW2[c*47+c2]; broadcast+coalesced
        int c2 = threadIdx.x;
        if (c2 < NCLS) {
            const float* prow = post + (size_t)b * 256;
            float s = 0.f;
#pragma unroll 8
            for (int c = 0; c < 256; c++)
                s = fmaf(prow[c], postW2[(size_t)c * NCLS + c2], s);
            wc[b * NCLS + c2] = s;
        }
    } else if (b == 256) {
        int c2 = threadIdx.x;
        if (c2 < NCLS) {
            float t = postb2[c2];
#pragma unroll 8
            for (int c = 0; c < 256; c++)
                t = fmaf(postb1[c], postW2[(size_t)c * NCLS + c2], t);
            bc[c2] = t;
        }
    } else if (b < 6657) {
        int idx = (b - 257) * 256 + threadIdx.x;
        int m = idx >> 16;
        int rem = idx & 65535;
        int n = rem & 255, k = rem >> 8;
        const float* W;
        int chunk;
        if (m < 3)       { W = linl + (size_t)m * 65536;       chunk = 0  + m * 8 + (k >> 6); }
        else if (m < 6)  { W = linr + (size_t)(m - 3) * 65536; chunk = 4  + (m - 3) * 8 + (k >> 6); }
        else if (m < 9)  { W = w1 + (size_t)(m - 6) * 65536;   chunk = 24 + (m - 6) * 4 + (k >> 6); }
        else if (m < 15) { W = wa + (size_t)(m - 9) * 65536;   chunk = 36 + (m - 9) * 4 + (k >> 6); }
        else if (m < 21) { W = wb + (size_t)(m - 15) * 65536;  chunk = 60 + (m - 15) * 4 + (k >> 6); }
        else             { W = w2 + (size_t)(m - 21) * 65536;  chunk = 84 + (m - 21) * 4 + (k >> 6); }
        float v = W[(size_t)k * 256 + n];
        unsigned off = (unsigned)chunk * 32768u + SWZ((unsigned)(n * 128 + (k & 63) * 2));
        dhi[off >> 1] = (unsigned short)bhi(v);
    } else {
        int idx = (b - 6657) * 256 + threadIdx.x;   // < NN*128 exactly
        int row = idx >> 7, p = idx & 127;
        float v0 = X[(size_t)row * 256 + p * 2];
        float v1 = X[(size_t)row * 256 + p * 2 + 1];
        img_write_hi(xih, (p * 2) >> 6, row, (p * 2) & 63, v0, v1);
    }
}

// ---------------- single-kernel CSR build (persistent grid + sw barrier) ----------------
static __device__ __forceinline__ void gridbar() {
    __syncthreads();
    __threadfence();
    if (threadIdx.x == 0) {
        unsigned arr = atomicAdd(&g_bar, 1u);
        unsigned target = (arr / CSRB + 1u) * CSRB;
        while (*(volatile unsigned*)&g_bar < target) { }
    }
    __syncthreads();
}

__global__ void csr_kernel(const int* __restrict__ src, const int* __restrict__ dst,
                           int* __restrict__ cnt, int* __restrict__ off,
                           int* __restrict__ cur, int* __restrict__ csr) {
    __shared__ int sdata[256];
    const int b = blockIdx.x, t = threadIdx.x;
    for (int e = b * 256 + t; e < EE; e += CSRB * 256)
        atomicAdd(&cnt[dst[e]], 1);
    gridbar();
    int n0 = (b * 256 + t) * 2;
    int c0 = (n0 < NN) ? cnt[n0] : 0;
    int c1 = (n0 + 1 < NN) ? cnt[n0 + 1] : 0;
    if (n0 < NN) cnt[n0] = 0;
    if (n0 + 1 < NN) cnt[n0 + 1] = 0;
    int ts = c0 + c1;
    sdata[t] = ts;
    __syncthreads();
#pragma unroll
    for (int o = 1; o < 256; o <<= 1) {
        int v = (t >= o) ? sdata[t - o] : 0;
        __syncthreads();
        sdata[t] += v;
        __syncthreads();
    }
    int bexcl = sdata[t] - ts;
    if (t == 255) g_partial[b] = sdata[t];
    gridbar();
    if (b == 0) {
        int v = (t < CSRB) ? g_partial[t] : 0;
        sdata[t] = v;
        __syncthreads();
#pragma unroll
        for (int o = 1; o < 256; o <<= 1) {
            int w = (t >= o) ? sdata[t - o] : 0;
            __syncthreads();
            sdata[t] += w;
            __syncthreads();
        }
        if (t < CSRB) g_pscan[t] = sdata[t] - v;
        if (t == 0) off[0] = 0;
    }
    gridbar();
    int base = g_pscan[b] + bexcl;
    if (n0 < NN) {
        cur[n0] = base;
        off[n0 + 1] = base + c0;
        if (n0 + 1 < NN) {
            cur[n0 + 1] = base + c0;
            if (n0 + 2 <= NN) off[n0 + 2] = base + c0 + c1;
        }
    }
    gridbar();
    for (int e = b * 256 + t; e < EE; e += CSRB * 256) {
        int p = atomicAdd(&cur[dst[e]], 1);
        csr[p] = src[e];
    }
}

// ---------------- gather (hi-only, 8-wide MLP) ----------------
__global__ void gather_img(const unsigned* __restrict__ xih,
                           const int* __restrict__ off, const int* __restrict__ csr,
                           unsigned* __restrict__ zih) {
    int w = (blockIdx.x * 256 + threadIdx.x) >> 5;
    int d = w >> 2, c = w & 3;
    if (d >= NN) return;
    int lane = threadIdx.x & 31;
    int b = off[d], e = off[d + 1];
    const unsigned* __restrict__ base = xih + (size_t)c * ROWSP * 32u;
    float s0 = 0.f, s1 = 0.f;
    int j = b;
    for (; j + 8 <= e; j += 8) {
        int r[8];
#pragma unroll
        for (int q = 0; q < 8; q++) r[q] = __ldg(&csr[j + q]);
        unsigned v[8];
#pragma unroll
        for (int q = 0; q < 8; q++)
            v[q] = __ldg(&base[(unsigned)r[q] * 32u + ((unsigned)lane ^ (((unsigned)r[q] & 7u) << 2))]);
#pragma unroll
        for (int q = 0; q < 8; q++) {
            s0 += bf2f((unsigned short)(v[q] & 0xffff));
            s1 += bf2f((unsigned short)(v[q] >> 16));
        }
    }
    for (; j + 2 <= e; j += 2) {
        int r0 = __ldg(&csr[j]), r1 = __ldg(&csr[j + 1]);
        unsigned v0 = __ldg(&base[(unsigned)r0 * 32u + ((unsigned)lane ^ (((unsigned)r0 & 7u) << 2))]);
        unsigned v1 = __ldg(&base[(unsigned)r1 * 32u + ((unsigned)lane ^ (((unsigned)r1 & 7u) << 2))]);
        s0 += bf2f((unsigned short)(v0 & 0xffff)) + bf2f((unsigned short)(v1 & 0xffff));
        s1 += bf2f((unsigned short)(v0 >> 16)) + bf2f((unsigned short)(v1 >> 16));
    }
    if (j < e) {
        int r0 = __ldg(&csr[j]);
        unsigned v0 = __ldg(&base[(unsigned)r0 * 32u + ((unsigned)lane ^ (((unsigned)r0 & 7u) << 2))]);
        s0 += bf2f((unsigned short)(v0 & 0xffff));
        s1 += bf2f((unsigned short)(v0 >> 16));
    }
    float iv = 1.f / fmaxf((float)(e - b), 1.f);
    img_write_hi(zih, c, d, lane * 2, s0 * iv, s1 * iv);
}

// ---- M64 MMA micro-kernel: one 8KB A chunk (64 rows, k64) vs one 32KB B chunk ----
// warp tile 16(M) x 128(N): wm0 = (wid&3)*16, wn0 = (wid>>2)*128. acc[16][4].
static __device__ __forceinline__ void mma_chunk(unsigned abase, unsigned bbase,
                                                 float (&acc)[16][4], int wm0, int wn0,
                                                 int lane) {
    const int lrow = lane & 15;
    const int lk = (lane >> 4) * 8;
#pragma unroll
    for (int ks = 0; ks < 4; ks++) {
        const int k0 = ks * 16;
        unsigned ahi[4];
        {
            unsigned off = SWZ((unsigned)((wm0 + lrow) * 128 + (k0 + lk) * 2));
            ldsm4(ahi, abase + off);
        }
#pragma unroll
        for (int hp = 0; hp < 4; hp++) {
            unsigned bb[2][4];
#pragma unroll
            for (int q = 0; q < 2; q++) {
                int g = hp * 2 + q;
                unsigned off = SWZ((unsigned)((wn0 + g * 16 + lrow) * 128 + (k0 + lk) * 2));
                ldsm4(bb[q], bbase + off);
            }
#pragma unroll
            for (int q = 0; q < 2; q++)
#pragma unroll
                for (int r0 = 0; r0 < 2; r0++)
                    mma16816(acc[(hp * 2 + q) * 2 + r0], ahi, bb[q][r0], bb[q][r0 + 2]);
        }
    }
}

// ---------------- fused layer kernel (M64, 256 threads, 2 CTAs/SM) ----------------
// 32 K-64 slots (+4 post): stage st = s>>2, A chunk = s&3.
// Stage order: cat-x, cat-z, w1, wa0, wb0, wa1, wb1, w2 [, post]
__global__ void __launch_bounds__(256, 2)
fused_layer(unsigned* __restrict__ ximg_hi, const unsigned* __restrict__ zimg_hi,
            SlotTab tab, int nslots,
            const float* __restrict__ bl, const float* __restrict__ br,
            const float* __restrict__ b1,
            const float* __restrict__ ba0, const float* __restrict__ g0,
            const float* __restrict__ be0, const float* __restrict__ bb0,
            const float* __restrict__ ba1, const float* __restrict__ g1,
            const float* __restrict__ be1, const float* __restrict__ bb1,
            const float* __restrict__ b2, const float* __restrict__ postb, float bnscale,
            unsigned* __restrict__ himg_hi, unsigned* __restrict__ himg_lo,
            float* __restrict__ pp) {
    extern __shared__ char smem[];
    const unsigned sb = smem_u32(smem);
    const int tid = threadIdx.x, wid = tid >> 5, lane = tid & 31;
    const int bm0 = blockIdx.x * 64;
    const int wm0 = (wid & 3) * 16;
    const int wn0 = (wid >> 2) * 128;
    const int tr = lane >> 2;
    const int tc2 = (lane & 3) * 2;
    const bool haspost = (nslots > 32);

    float acc[16][4];
    auto zero_acc = [&]() {
#pragma unroll
        for (int a = 0; a < 16; a++)
#pragma unroll
            for (int c = 0; c < 4; c++) acc[a][c] = 0.f;
    };
    zero_acc();

    auto issue_B = [&](int s) {   // 32KB, no commit
        if (s >= nslots) return;
        const char* src = (const char*)tab.p[s];
        unsigned dstb = sb + FS_B + (unsigned)(s & 1) * 32768u;
#pragma unroll
        for (int i = 0; i < 8; i++) {
            int u = tid + i * 256;
            CPA(dstb + u * 16, src + u * 16);
        }
    };
    auto issue_z = [&](int c) {   // 8KB hi-only into A chunk c
        const char* gh = (const char*)(zimg_hi + ((size_t)c * ROWSP + bm0) * 32);
        unsigned cb = sb + (unsigned)c * 8192u;
#pragma unroll
        for (int i = 0; i < 2; i++) {
            int u = tid + i * 256;
            CPA(cb + u * 16, gh + u * 16);
        }
    };
    auto slot = [&](int s, int ah, int zc) {
        cp_wait<0>();
        __syncthreads();
        issue_B(s + 1);
        if (zc >= 0) issue_z(zc);
        CP_COMMIT();
        mma_chunk(sb + (unsigned)ah * 8192u, sb + FS_B + (unsigned)(s & 1) * 32768u,
                  acc, wm0, wn0, lane);
    };
    auto run4 = [&](int s0) {
#pragma unroll 1
        for (int c = 0; c < 4; c++) slot(s0 + c, c, -1);
    };
    auto conv_img = [&]() {   // acc -> smem A image (hi only); caller syncs BEFORE
#pragma unroll
        for (int ni = 0; ni < 16; ni++) {
            int cg = wn0 + ni * 8 + tc2;
            unsigned cb = (unsigned)(cg >> 6) * 8192u;
            int lc = cg & 63;
            float* d = acc[ni];
            unsigned off = SWZ((unsigned)((wm0 + tr) * 128 + lc * 2));
            *(unsigned*)(smem + cb + off) = bhi(d[0]) | (bhi(d[1]) << 16);
            off = SWZ((unsigned)((wm0 + 8 + tr) * 128 + lc * 2));
            *(unsigned*)(smem + cb + off) = bhi(d[2]) | (bhi(d[3]) << 16);
        }
    };

    // ---- prologue: x image (hi only, 4x8KB) + B slot 0 ----
#pragma unroll
    for (int c = 0; c < 4; c++) {
        const char* gh = (const char*)(ximg_hi + ((size_t)c * ROWSP + bm0) * 32);
        unsigned cb = sb + (unsigned)c * 8192u;
#pragma unroll
        for (int i = 0; i < 2; i++) {
            int u = tid + i * 256;
            CPA(cb + u * 16, gh + u * 16);
        }
    }
    CP_COMMIT();
    issue_B(0);
    CP_COMMIT();

    // ---- cat: slots 0-3 (x), 4-7 (z); z chunk s-1 prefetched at slots 1..4 ----
#pragma unroll 1
    for (int s = 0; s < 8; s++)
        slot(s, s & 3, (s >= 1 && s <= 4) ? (s - 1) : -1);
    __syncthreads();
#pragma unroll
    for (int ni = 0; ni < 16; ni++) {
        int cg = wn0 + ni * 8 + tc2;
        float* d = acc[ni];
        float a0 = bl[cg] + br[cg], a1 = bl[cg + 1] + br[cg + 1];
        d[0] += a0; d[1] += a1; d[2] += a0; d[3] += a1;
    }
    conv_img(); zero_acc();

    // ---- w1: slots 8-11 -> h0 (write himg) ----
    run4(8);
    __syncthreads();
#pragma unroll
    for (int ni = 0; ni < 16; ni++) {
        int cg = wn0 + ni * 8 + tc2;
        float* d = acc[ni];
        d[0] += b1[cg]; d[1] += b1[cg + 1]; d[2] += b1[cg]; d[3] += b1[cg + 1];
        int ra = bm0 + wm0 + tr;
        img_write2(himg_hi, himg_lo, cg >> 6, ra, cg & 63, d[0], d[1]);
        img_write2(himg_hi, himg_lo, cg >> 6, ra + 8, cg & 63, d[2], d[3]);
    }
    conv_img(); zero_acc();

    // ---- blocks: wa j: 12+8j, wb j: 16+8j ----
#pragma unroll 1
    for (int j = 0; j < 2; j++) {
        const float* ba = j ? ba1 : ba0;
        const float* gg = j ? g1 : g0;
        const float* be = j ? be1 : be0;
        const float* bb = j ? bb1 : bb0;
        run4(12 + j * 8);
        __syncthreads();
#pragma unroll
        for (int ni = 0; ni < 16; ni++) {
            int cg = wn0 + ni * 8 + tc2;
            float* d = acc[ni];
            float ga = gg[cg], gb = gg[cg + 1], ea = be[cg], eb = be[cg + 1];
            float a0 = ba[cg], a1 = ba[cg + 1];
            d[0] = fmaf(ga, fmaxf(d[0] + a0, 0.f) * bnscale, ea);
            d[1] = fmaf(gb, fmaxf(d[1] + a1, 0.f) * bnscale, eb);
            d[2] = fmaf(ga, fmaxf(d[2] + a0, 0.f) * bnscale, ea);
            d[3] = fmaf(gb, fmaxf(d[3] + a1, 0.f) * bnscale, eb);
        }
        conv_img(); zero_acc();
        run4(16 + j * 8);
        __syncthreads();
#pragma unroll
        for (int ni = 0; ni < 16; ni++) {
            int cg = wn0 + ni * 8 + tc2;
            float* d = acc[ni];
            int ra = bm0 + wm0 + tr;
            float2 ha = img_read2(himg_hi, himg_lo, cg >> 6, ra, cg & 63);
            float2 hb = img_read2(himg_hi, himg_lo, cg >> 6, ra + 8, cg & 63);
            d[0] += bb[cg] + ha.x; d[1] += bb[cg + 1] + ha.y;
            d[2] += bb[cg] + hb.x; d[3] += bb[cg + 1] + hb.y;
            if (j == 0) {
                img_write2(himg_hi, himg_lo, cg >> 6, ra, cg & 63, d[0], d[1]);
                img_write2(himg_hi, himg_lo, cg >> 6, ra + 8, cg & 63, d[2], d[3]);
            }
        }
        conv_img(); zero_acc();
    }

    // ---- w2: slots 28-31, normalize + relu ----
    run4(28);
    __syncthreads();
#pragma unroll
    for (int ni = 0; ni < 16; ni++) {
        int cg = wn0 + ni * 8 + tc2;
        float* d = acc[ni];
        d[0] += b2[cg]; d[1] += b2[cg + 1]; d[2] += b2[cg]; d[3] += b2[cg + 1];
    }
    {
        float* rsum = (float*)(smem + RSUM_OFF);   // [64 rows][2 halves]
        float ps0 = 0.f, ps1 = 0.f;
#pragma unroll
        for (int ni = 0; ni < 16; ni++) {
            float* d = acc[ni];
            ps0 = fmaf(d[0], d[0], fmaf(d[1], d[1], ps0));
            ps1 = fmaf(d[2], d[2], fmaf(d[3], d[3], ps1));
        }
#pragma unroll
        for (int o = 1; o <= 2; o <<= 1) {
            ps0 += __shfl_xor_sync(0xffffffffu, ps0, o);
            ps1 += __shfl_xor_sync(0xffffffffu, ps1, o);
        }
        int half = wn0 >> 7;
        if ((lane & 3) == 0) {
            rsum[(wm0 + tr) * 2 + half] = ps0;
            rsum[(wm0 + 8 + tr) * 2 + half] = ps1;
        }
        __syncthreads();
        int r0 = wm0 + tr, r1 = r0 + 8;
        float s0 = rsum[r0 * 2] + rsum[r0 * 2 + 1];
        float s1 = rsum[r1 * 2] + rsum[r1 * 2 + 1];
        float c0 = 1.f / fmaxf(sqrtf(s0), 1e-12f);
        float c1 = 1.f / fmaxf(sqrtf(s1), 1e-12f);
#pragma unroll
        for (int ni = 0; ni < 16; ni++) {
            float* d = acc[ni];
            d[0] = fmaxf(d[0] * c0, 0.f); d[1] = fmaxf(d[1] * c0, 0.f);
            d[2] = fmaxf(d[2] * c1, 0.f); d[3] = fmaxf(d[3] * c1, 0.f);
        }
    }
    if (!haspost) {
#pragma unroll
        for (int ni = 0; ni < 16; ni++) {
            int cg = wn0 + ni * 8 + tc2;
            int ra = bm0 + wm0 + tr;
            float* d = acc[ni];
            img_write_hi(ximg_hi, cg >> 6, ra, cg & 63, d[0], d[1]);
            img_write_hi(ximg_hi, cg >> 6, ra + 8, cg & 63, d[2], d[3]);
        }
        return;
    }
    // ---- post stage (unused in this config; kept for codegen parity) ----
    conv_img(); zero_acc();
    __syncthreads();
    run4(32);
    __syncthreads();
#pragma unroll
    for (int ni = 0; ni < 16; ni++) {
        int cg = wn0 + ni * 8 + tc2;
        int ra = bm0 + wm0 + tr;
        int rb = ra + 8;
        float* d = acc[ni];
        float v0 = d[0] + postb[cg], v1 = d[1] + postb[cg + 1];
        float v2 = d[2] + postb[cg], v3 = d[3] + postb[cg + 1];
        if (ra < NN) *(float2*)(pp + (size_t)ra * 256 + cg) = make_float2(v0, v1);
        if (rb < NN) *(float2*)(pp + (size_t)rb * 256 + cg) = make_float2(v2, v3);
    }
}

// ---------------- head: logits = x @ Wc + bc, log_softmax (reads x image) ----------------
__global__ void head_kernel(const unsigned* __restrict__ xih, const float* __restrict__ Wc,
                            const float* __restrict__ bc, float* __restrict__ out) {
    __shared__ float sW[256 * NCLS];
    __shared__ float sb[NCLS];
    int tid = threadIdx.x;
    for (int i = tid; i < 256 * NCLS; i += 256) sW[i] = Wc[i];
    if (tid < NCLS) sb[tid] = bc[tid];
    __syncthreads();

    int wid = tid >> 5, lane = tid & 31;
    int r = blockIdx.x * 8 + wid;
    if (r >= NN) return;

    // lane holds cols {c*64 + lane*2, +1} for chunks c=0..3
    float hreg[8];
#pragma unroll
    for (int c = 0; c < 4; c++) {
        unsigned v = __ldg(&xih[((size_t)c * ROWSP + r) * 32u +
                                ((unsigned)lane ^ (((unsigned)r & 7u) << 2))]);
        hreg[c * 2 + 0] = bf2f((unsigned short)(v & 0xffff));
        hreg[c * 2 + 1] = bf2f((unsigned short)(v >> 16));
    }

    int c0 = lane;
    int c1 = lane + 32;
    int c1m = (c1 < NCLS) ? c1 : (NCLS - 1);
    float acc0 = sb[c0];
    float acc1 = sb[c1m];
#pragma unroll
    for (int e = 0; e < 8; e++) {
        int ch = e >> 1, hf = e & 1;
        for (int l = 0; l < 32; l++) {
            float hv = __shfl_sync(0xffffffffu, hreg[e], l);
            int k = ch * 64 + l * 2 + hf;
            acc0 = fmaf(hv, sW[k * NCLS + c0], acc0);
            acc1 = fmaf(hv, sW[k * NCLS + c1m], acc1);
        }
    }
    float m = fmaxf(acc0, (c1 < NCLS) ? acc1 : -3.4e38f);
#pragma unroll
    for (int o = 16; o > 0; o >>= 1) m = fmaxf(m, __shfl_xor_sync(0xffffffffu, m, o));
    float es = expf(acc0 - m) + ((c1 < NCLS) ? expf(acc1 - m) : 0.f);
#pragma unroll
    for (int o = 16; o > 0; o >>= 1) es += __shfl_xor_sync(0xffffffffu, es, o);
    float lse = m + logf(es);
    out[(size_t)r * NCLS + c0] = acc0 - lse;
    if (c1 < NCLS) out[(size_t)r * NCLS + c1] = acc1 - lse;
}

// ---------------- host orchestration ----------------
extern "C" void kernel_launch(void* const* d_in, const int* in_sizes, int n_in,
                              void* d_out, int out_size) {
    const float* x_in      = (const float*)d_in[0];
    const int* ei          = (const int*)d_in[1];
    const float* lin_l_W   = (const float*)d_in[2];
    const float* lin_l_b   = (const float*)d_in[3];
    const float* lin_r_W   = (const float*)d_in[4];
    const float* lin_r_b   = (const float*)d_in[5];
    const float* mlp_W1    = (const float*)d_in[6];
    const float* mlp_b1    = (const float*)d_in[7];
    const float* blk_Wa    = (const float*)d_in[8];
    const float* blk_ba    = (const float*)d_in[9];
    const float* blk_gamma = (const float*)d_in[10];
    const float* blk_beta  = (const float*)d_in[11];
    const float* blk_Wb    = (const float*)d_in[12];
    const float* blk_bb    = (const float*)d_in[13];
    const float* mlp_W2    = (const float*)d_in[14];
    const float* mlp_b2    = (const float*)d_in[15];
    const float* post_W1   = (const float*)d_in[16];
    const float* post_b1   = (const float*)d_in[17];
    const float* post_W2   = (const float*)d_in[18];
    const float* post_b2   = (const float*)d_in[19];
    float* out = (float*)d_out;

    uint4* whi;
    unsigned *xih, *zih, *hih, *hil;
    float *wc, *bc;
    int *cnti, *offp, *curp, *csrp;
    cudaGetSymbolAddress((void**)&whi, g_whi4);
    cudaGetSymbolAddress((void**)&xih, g_ximg_hi);
    cudaGetSymbolAddress((void**)&zih, g_zimg_hi);
    cudaGetSymbolAddress((void**)&hih, g_himg_hi);
    cudaGetSymbolAddress((void**)&hil, g_himg_lo);
    cudaGetSymbolAddress((void**)&wc, g_wc);
    cudaGetSymbolAddress((void**)&bc, g_bc);
    cudaGetSymbolAddress((void**)&cnti, g_cnti);
    cudaGetSymbolAddress((void**)&offp, g_off);
    cudaGetSymbolAddress((void**)&curp, g_cur);
    cudaGetSymbolAddress((void**)&csrp, g_csr);

    cudaFuncSetAttribute(fused_layer, cudaFuncAttributeMaxDynamicSharedMemorySize, FSMEM);

    const float bnscale = rsqrtf(1.0f + 1e-5f);
    const int* src = ei;
    const int* dst = ei + EE;

    // 1: setup (Wc/bc first [overlapped] + weights + x image)
    setup_kernel<<<31657, 256>>>(
        lin_l_W, lin_r_W, mlp_W1, blk_Wa, blk_Wb, mlp_W2,
        post_W1, post_b1, post_W2, post_b2, x_in,
        (unsigned short*)whi, xih, wc, bc);
    // 2: CSR (count+scan+fill, one persistent kernel)
    csr_kernel<<<CSRB, 256>>>(src, dst, cnti, offp, curp, csrp);

    for (int i = 0; i < NLAYER; i++) {
        // 3: gather (hi only, 8-wide)
        gather_img<<<(NN + 1) / 2, 256>>>(xih, offp, csrp, zih);

        SlotTab tab;
        int s = 0;
        auto push = [&](int base) {   // one 256x256 matrix = 4 slots of 32KB
            for (int c = 0; c < 4; c++) tab.p[s++] = whi + (size_t)(base + c) * 2048;
        };
        push(i * 8);                 // cat-x (lin_l)           slots 0-3
        push(i * 8 + 4);             // cat-z (lin_r)           slots 4-7
        push(24 + i * 4);            // w1                      slots 8-11
        push(36 + (2 * i) * 4);      // wa0                     slots 12-15
        push(60 + (2 * i) * 4);      // wb0                     slots 16-19
        push(36 + (2 * i + 1) * 4);  // wa1                     slots 20-23
        push(60 + (2 * i + 1) * 4);  // wb1                     slots 24-27
        push(84 + i * 4);            // w2                      slots 28-31

        size_t bo0 = ((size_t)i * 2) * 256, bo1 = ((size_t)i * 2 + 1) * 256;
        // 4: fused layer (nslots=32 for ALL layers -> !haspost path)
        fused_layer<<<NB2, 256, FSMEM>>>(
            xih, zih, tab, 32,
            lin_l_b + (size_t)i * 256, lin_r_b + (size_t)i * 256,
            mlp_b1 + (size_t)i * 256,
            blk_ba + bo0, blk_gamma + bo0, blk_beta + bo0, blk_bb + bo0,
            blk_ba + bo1, blk_gamma + bo1, blk_beta + bo1, blk_bb + bo1,
            mlp_b2 + (size_t)i * 256, post_b1, bnscale,
            hih, hil, nullptr);
    }

    head_kernel<<<(NN + 7) / 8, 256>>>(xih, wc, bc, out);
}